// round 2
// baseline (speedup 1.0000x reference)
#include <cuda_runtime.h>
#include <cstdint>
#include <cstddef>

// Bidirectional tanh RNN, fully fused persistent kernel.
// N=8, L=4096, C=256, H=256.  16 independent sequences (8 batch x 2 dir).
// One cluster of 8 CTAs per sequence; CTA owns 32 hidden units; weights in registers.

constexpr int L_DIM   = 4096;
constexpr int C_DIM   = 256;
constexpr int H_DIM   = 256;
constexpr int CLUSTER = 8;
constexpr int UNITS_PER_CTA = H_DIM / CLUSTER;   // 32
constexpr int THREADS = 256;                      // 8 threads per unit

__device__ __forceinline__ uint32_t smem_u32(const void* p) {
    return (uint32_t)__cvta_generic_to_shared(p);
}

__device__ __forceinline__ float fast_tanh(float z) {
    // tanh(z) = 1 - 2/(exp(2z)+1); __expf -> MUFU.EX2 path, ~1e-6 rel err.
    float e = __expf(2.0f * z);
    return 1.0f - 2.0f / (e + 1.0f);
}

__global__ void __launch_bounds__(THREADS, 1) __cluster_dims__(CLUSTER, 1, 1)
rnn_bidir_kernel(const float* __restrict__ x,
                 const float* __restrict__ Wih,
                 const float* __restrict__ Whh,
                 const float* __restrict__ bih,
                 const float* __restrict__ bhh,
                 const float* __restrict__ init_states,
                 float* __restrict__ out)
{
    __shared__ __align__(16) float h_buf[2][H_DIM];
    __shared__ __align__(16) float x_buf[2][C_DIM];

    const int tid  = threadIdx.x;
    const int w    = tid >> 5;
    const int lane = tid & 31;
    const int jj   = (w << 2) | (lane & 3);   // 0..31 : unit within CTA slice
    const int c    = lane >> 2;               // 0..7  : K-chunk (32 elems each)

    uint32_t rank_u;
    asm("mov.u32 %0, %%cluster_ctarank;" : "=r"(rank_u));
    const int rank = (int)rank_u;

    const int seq = blockIdx.x >> 3;          // cluster id: 0..15
    const int n   = seq & 7;                  // batch index
    const int dir = seq >> 3;                 // 0 = forward, 1 = reverse

    const int j  = rank * UNITS_PER_CTA + jj; // global hidden unit 0..255
    const int i0 = c * 32;                    // K-chunk start

    // ---- load weight slices into registers (one-time) ----
    float wh[32], wi[32];
    {
        const float4* p = reinterpret_cast<const float4*>(Whh + (size_t)j * H_DIM + i0);
        const float4* q = reinterpret_cast<const float4*>(Wih + (size_t)j * C_DIM + i0);
#pragma unroll
        for (int k = 0; k < 8; k++) {
            float4 a = p[k];
            wh[4*k+0] = a.x; wh[4*k+1] = a.y; wh[4*k+2] = a.z; wh[4*k+3] = a.w;
            float4 b = q[k];
            wi[4*k+0] = b.x; wi[4*k+1] = b.y; wi[4*k+2] = b.z; wi[4*k+3] = b.w;
        }
    }
    const float bsum = bih[j] + bhh[j];

    const float* xbase = x + (size_t)n * L_DIM * C_DIM;

    // ---- init h and stage x row for step 0 ----
    if (tid < H_DIM) h_buf[0][tid] = init_states[tid];
    {
        const int ll0 = dir ? (L_DIM - 1) : 0;
        if (tid < 64)
            reinterpret_cast<float4*>(x_buf[0])[tid] =
                reinterpret_cast<const float4*>(xbase + (size_t)ll0 * C_DIM)[tid];
    }
    __syncthreads();
    // Full cluster sync before any DSMEM traffic (all CTAs resident + buffers init'd).
    asm volatile("barrier.cluster.arrive.aligned;" ::: "memory");
    asm volatile("barrier.cluster.wait.aligned;"   ::: "memory");

    for (int s = 0; s < L_DIM; ++s) {
        const int pb = s & 1;
        const int nb = pb ^ 1;

        // ---- prefetch next x row into registers (hidden under compute) ----
        float4 xn = make_float4(0.f, 0.f, 0.f, 0.f);
        {
            const int sn  = (s + 1 < L_DIM) ? (s + 1) : s;
            const int lln = dir ? (L_DIM - 1 - sn) : sn;
            if (tid < 64)
                xn = reinterpret_cast<const float4*>(xbase + (size_t)lln * C_DIM)[tid];
        }

        // ---- u = W_ih . x_t  (independent of h: overlaps the barrier wait) ----
        float a0 = 0.f, a1 = 0.f, a2 = 0.f, a3 = 0.f;
        {
            const float4* xv = reinterpret_cast<const float4*>(x_buf[pb] + i0);
#pragma unroll
            for (int k = 0; k < 8; k++) {
                float4 t = xv[k];
                a0 = fmaf(wi[4*k+0], t.x, a0);
                a1 = fmaf(wi[4*k+1], t.y, a1);
                a2 = fmaf(wi[4*k+2], t.z, a2);
                a3 = fmaf(wi[4*k+3], t.w, a3);
            }
        }

        // ---- wait for h(s-1) from all peers (skip on s=0: local init) ----
        if (s) asm volatile("barrier.cluster.wait.aligned;" ::: "memory");

        // ---- v = W_hh . h ----
        {
            const float4* hv = reinterpret_cast<const float4*>(h_buf[pb] + i0);
#pragma unroll
            for (int k = 0; k < 8; k++) {
                float4 t = hv[k];
                a0 = fmaf(wh[4*k+0], t.x, a0);
                a1 = fmaf(wh[4*k+1], t.y, a1);
                a2 = fmaf(wh[4*k+2], t.z, a2);
                a3 = fmaf(wh[4*k+3], t.w, a3);
            }
        }

        // ---- reduce across the 8 chunk-lanes (bits 2..4 of lane) ----
        float acc = (a0 + a1) + (a2 + a3);
        acc += __shfl_xor_sync(0xffffffffu, acc, 16);
        acc += __shfl_xor_sync(0xffffffffu, acc, 8);
        acc += __shfl_xor_sync(0xffffffffu, acc, 4);

        const float hn = fast_tanh(acc + bsum);

        // ---- reducer lanes: broadcast h_new to all 8 CTAs + write output ----
        if (c == 0) {
            const uint32_t la = smem_u32(&h_buf[nb][j]);
#pragma unroll
            for (int r = 0; r < CLUSTER; r++) {
                uint32_t ra;
                asm volatile("mapa.shared::cluster.u32 %0, %1, %2;"
                             : "=r"(ra) : "r"(la), "r"(r));
                asm volatile("st.shared::cluster.f32 [%0], %1;"
                             :: "r"(ra), "f"(hn) : "memory");
            }
            const int ll = dir ? (L_DIM - 1 - s) : s;
            out[((size_t)(n * L_DIM + ll)) * (2 * H_DIM) + dir * H_DIM + j] = hn;
        }

        // ---- commit staged x row for step s+1 ----
        if (tid < 64) reinterpret_cast<float4*>(x_buf[nb])[tid] = xn;

        __syncthreads();  // x_buf + local h visibility within CTA
        // Release: orders the st.shared::cluster pushes before peers' next wait.
        asm volatile("barrier.cluster.arrive.aligned;" ::: "memory");
    }
    // Balance final arrive; also guarantees no peer is still writing our smem.
    asm volatile("barrier.cluster.wait.aligned;" ::: "memory");
}

extern "C" void kernel_launch(void* const* d_in, const int* in_sizes, int n_in,
                              void* d_out, int out_size)
{
    (void)in_sizes; (void)n_in; (void)out_size;
    const float* x    = (const float*)d_in[0];
    const float* Wih  = (const float*)d_in[1];
    const float* Whh  = (const float*)d_in[2];
    const float* bih  = (const float*)d_in[3];
    const float* bhh  = (const float*)d_in[4];
    const float* init = (const float*)d_in[5];
    float* out = (float*)d_out;

    rnn_bidir_kernel<<<16 * CLUSTER, THREADS>>>(x, Wih, Whh, bih, bhh, init, out);
}

// round 3
// speedup vs baseline: 1.4263x; 1.4263x over previous
#include <cuda_runtime.h>
#include <cstdint>
#include <cstddef>

// Bidirectional tanh RNN, fused persistent cluster kernel, mbarrier+st.async sync.
// N=8, L=4096, C=256, H=256. 16 sequences (8 batch x 2 dir) x 8-CTA clusters.
// CTA owns 32 hidden units; W slices live in registers; h exchanged via DSMEM
// st.async with transaction-counted mbarriers (no cluster barrier in the loop).

constexpr int L_DIM   = 4096;
constexpr int C_DIM   = 256;
constexpr int H_DIM   = 256;
constexpr int CLUSTER = 8;
constexpr int UNITS_PER_CTA = H_DIM / CLUSTER;   // 32
constexpr int THREADS = 256;                      // 8 threads per unit
constexpr unsigned TX_BYTES = H_DIM * 4;          // 1024 B per phase (256 f32 stores)

__device__ __forceinline__ uint32_t smem_u32(const void* p) {
    return (uint32_t)__cvta_generic_to_shared(p);
}

__device__ __forceinline__ float fast_tanh(float z) {
    // tanh(z) = 1 - 2/(exp(2z)+1); MUFU path, ~1e-6 rel err.
    float e = __expf(2.0f * z);
    return 1.0f - 2.0f / (e + 1.0f);
}

__device__ __forceinline__ void mbar_wait_cluster(uint32_t mbar, uint32_t parity) {
    asm volatile(
        "{\n\t"
        ".reg .pred P1;\n\t"
        "WAIT_LOOP_%=:\n\t"
        "mbarrier.try_wait.parity.acquire.cluster.shared::cta.b64 P1, [%0], %1;\n\t"
        "@P1 bra.uni WAIT_DONE_%=;\n\t"
        "bra.uni WAIT_LOOP_%=;\n\t"
        "WAIT_DONE_%=:\n\t"
        "}"
        :: "r"(mbar), "r"(parity) : "memory");
}

__device__ __forceinline__ void mbar_expect(uint32_t mbar) {
    asm volatile("mbarrier.arrive.expect_tx.shared.b64 _, [%0], %1;"
                 :: "r"(mbar), "r"(TX_BYTES) : "memory");
}

__device__ __forceinline__ void st_async_f32(uint32_t raddr, float v, uint32_t rmbar) {
    asm volatile(
        "st.async.shared::cluster.mbarrier::complete_tx::bytes.f32 [%0], %1, [%2];"
        :: "r"(raddr), "f"(v), "r"(rmbar) : "memory");
}

__global__ void __launch_bounds__(THREADS, 1) __cluster_dims__(CLUSTER, 1, 1)
rnn_bidir_kernel(const float* __restrict__ x,
                 const float* __restrict__ Wih,
                 const float* __restrict__ Whh,
                 const float* __restrict__ bih,
                 const float* __restrict__ bhh,
                 const float* __restrict__ init_states,
                 float* __restrict__ out)
{
    __shared__ __align__(16) float h_buf[2][H_DIM];
    __shared__ __align__(16) float x_buf[2][C_DIM];
    __shared__ __align__(8)  uint64_t mbar[2];

    const int tid  = threadIdx.x;
    const int w    = tid >> 5;
    const int lane = tid & 31;
    const int jj   = (w << 2) | (lane & 3);   // 0..31 : unit within CTA slice
    const int c    = lane >> 2;               // 0..7  : K-chunk (32 elems each)

    uint32_t rank_u;
    asm("mov.u32 %0, %%cluster_ctarank;" : "=r"(rank_u));
    const int rank = (int)rank_u;

    const int seq = blockIdx.x >> 3;          // 0..15
    const int n   = seq & 7;                  // batch index
    const int dir = seq >> 3;                 // 0 = forward, 1 = reverse

    const int j  = rank * UNITS_PER_CTA + jj; // global hidden unit
    const int i0 = c * 32;                    // K-chunk start

    // ---- weight slices into registers ----
    float wh[32], wi[32];
    {
        const float4* p = reinterpret_cast<const float4*>(Whh + (size_t)j * H_DIM + i0);
        const float4* q = reinterpret_cast<const float4*>(Wih + (size_t)j * C_DIM + i0);
#pragma unroll
        for (int k = 0; k < 8; k++) {
            float4 a = p[k];
            wh[4*k+0] = a.x; wh[4*k+1] = a.y; wh[4*k+2] = a.z; wh[4*k+3] = a.w;
            float4 b = q[k];
            wi[4*k+0] = b.x; wi[4*k+1] = b.y; wi[4*k+2] = b.z; wi[4*k+3] = b.w;
        }
    }
    const float bsum = bih[j] + bhh[j];
    const float* xbase = x + (size_t)n * L_DIM * C_DIM;

    const uint32_t mb0 = smem_u32(&mbar[0]);
    const uint32_t mb1 = smem_u32(&mbar[1]);

    // ---- mbarrier init + pre-arm phase 0 of both ----
    if (tid == 0) {
        asm volatile("mbarrier.init.shared.b64 [%0], 1;" :: "r"(mb0) : "memory");
        asm volatile("mbarrier.init.shared.b64 [%0], 1;" :: "r"(mb1) : "memory");
        asm volatile("fence.mbarrier_init.release.cluster;" ::: "memory");
        mbar_expect(mb0);   // phase 0 <- stores of step 1
        mbar_expect(mb1);   // phase 0 <- stores of step 0
    }

    // ---- init h, stage x row 0, prefetch x row 1 ----
    if (tid < H_DIM) h_buf[0][tid] = init_states[tid];
    float4 xn = make_float4(0.f, 0.f, 0.f, 0.f);
    if (tid < 64) {
        const int ll0 = dir ? (L_DIM - 1) : 0;
        reinterpret_cast<float4*>(x_buf[0])[tid] =
            reinterpret_cast<const float4*>(xbase + (size_t)ll0 * C_DIM)[tid];
        const int ll1 = dir ? (L_DIM - 2) : 1;
        xn = reinterpret_cast<const float4*>(xbase + (size_t)ll1 * C_DIM)[tid];
    }
    __syncthreads();
    // One-time cluster sync: all CTAs resident, mbarriers initialized+armed
    // before any st.async traffic.
    asm volatile("barrier.cluster.arrive.aligned;" ::: "memory");
    asm volatile("barrier.cluster.wait.aligned;"   ::: "memory");

    // ---- precompute remote DSMEM addresses (used by reducer lanes) ----
    uint32_t rh0[CLUSTER], rh1[CLUSTER], rm0[CLUSTER], rm1[CLUSTER];
    {
        const uint32_t lh0 = smem_u32(&h_buf[0][j]);
        const uint32_t lh1 = smem_u32(&h_buf[1][j]);
#pragma unroll
        for (int r = 0; r < CLUSTER; r++) {
            asm volatile("mapa.shared::cluster.u32 %0, %1, %2;" : "=r"(rh0[r]) : "r"(lh0), "r"(r));
            asm volatile("mapa.shared::cluster.u32 %0, %1, %2;" : "=r"(rh1[r]) : "r"(lh1), "r"(r));
            asm volatile("mapa.shared::cluster.u32 %0, %1, %2;" : "=r"(rm0[r]) : "r"(mb0), "r"(r));
            asm volatile("mapa.shared::cluster.u32 %0, %1, %2;" : "=r"(rm1[r]) : "r"(mb1), "r"(r));
        }
    }

    uint32_t ph0 = 0, ph1 = 0;

    for (int s = 0; s < L_DIM; s += 2) {
        // ================= even step s : read buf0, write buf1 (mb1) ===========
        {
            float a0 = 0.f, a1 = 0.f, a2 = 0.f, a3 = 0.f;
            {   // u = W_ih . x_s  (h-independent; runs ahead of the wait)
                const float4* xv = reinterpret_cast<const float4*>(x_buf[0] + i0);
#pragma unroll
                for (int k = 0; k < 8; k++) {
                    float4 t = xv[k];
                    a0 = fmaf(wi[4*k+0], t.x, a0);
                    a1 = fmaf(wi[4*k+1], t.y, a1);
                    a2 = fmaf(wi[4*k+2], t.z, a2);
                    a3 = fmaf(wi[4*k+3], t.w, a3);
                }
            }
            // commit row s+1 -> x_buf[1]; prefetch row s+2
            if (tid < 64) {
                reinterpret_cast<float4*>(x_buf[1])[tid] = xn;
                const int sn  = (s + 2 < L_DIM) ? s + 2 : L_DIM - 1;
                const int lln = dir ? (L_DIM - 1 - sn) : sn;
                xn = reinterpret_cast<const float4*>(xbase + (size_t)lln * C_DIM)[tid];
            }
            __syncthreads();

            if (s) {
                mbar_wait_cluster(mb0, ph0);
                ph0 ^= 1u;
                if (tid == 0) mbar_expect(mb0);   // re-arm for stores of step s+1
            }
            {   // v += W_hh . h_s  (h_buf[0])
                const float4* hv = reinterpret_cast<const float4*>(h_buf[0] + i0);
#pragma unroll
                for (int k = 0; k < 8; k++) {
                    float4 t = hv[k];
                    a0 = fmaf(wh[4*k+0], t.x, a0);
                    a1 = fmaf(wh[4*k+1], t.y, a1);
                    a2 = fmaf(wh[4*k+2], t.z, a2);
                    a3 = fmaf(wh[4*k+3], t.w, a3);
                }
            }
            float acc = (a0 + a1) + (a2 + a3);
            acc += __shfl_xor_sync(0xffffffffu, acc, 16);
            acc += __shfl_xor_sync(0xffffffffu, acc, 8);
            acc += __shfl_xor_sync(0xffffffffu, acc, 4);
            const float hn = fast_tanh(acc + bsum);

            if (c == 0) {
#pragma unroll
                for (int r = 0; r < CLUSTER; r++) st_async_f32(rh1[r], hn, rm1[r]);
                const int ll = dir ? (L_DIM - 1 - s) : s;
                out[((size_t)(n * L_DIM + ll)) * (2 * H_DIM) + dir * H_DIM + j] = hn;
            }
        }
        // ================= odd step s+1 : read buf1, write buf0 (mb0) ==========
        {
            const int so = s + 1;
            float a0 = 0.f, a1 = 0.f, a2 = 0.f, a3 = 0.f;
            {
                const float4* xv = reinterpret_cast<const float4*>(x_buf[1] + i0);
#pragma unroll
                for (int k = 0; k < 8; k++) {
                    float4 t = xv[k];
                    a0 = fmaf(wi[4*k+0], t.x, a0);
                    a1 = fmaf(wi[4*k+1], t.y, a1);
                    a2 = fmaf(wi[4*k+2], t.z, a2);
                    a3 = fmaf(wi[4*k+3], t.w, a3);
                }
            }
            // commit row s+2 -> x_buf[0]; prefetch row s+3
            if (tid < 64) {
                reinterpret_cast<float4*>(x_buf[0])[tid] = xn;
                const int sn  = (so + 2 < L_DIM) ? so + 2 : L_DIM - 1;
                const int lln = dir ? (L_DIM - 1 - sn) : sn;
                xn = reinterpret_cast<const float4*>(xbase + (size_t)lln * C_DIM)[tid];
            }
            __syncthreads();

            mbar_wait_cluster(mb1, ph1);
            ph1 ^= 1u;
            if (tid == 0) mbar_expect(mb1);       // re-arm for stores of step s+2
            {
                const float4* hv = reinterpret_cast<const float4*>(h_buf[1] + i0);
#pragma unroll
                for (int k = 0; k < 8; k++) {
                    float4 t = hv[k];
                    a0 = fmaf(wh[4*k+0], t.x, a0);
                    a1 = fmaf(wh[4*k+1], t.y, a1);
                    a2 = fmaf(wh[4*k+2], t.z, a2);
                    a3 = fmaf(wh[4*k+3], t.w, a3);
                }
            }
            float acc = (a0 + a1) + (a2 + a3);
            acc += __shfl_xor_sync(0xffffffffu, acc, 16);
            acc += __shfl_xor_sync(0xffffffffu, acc, 8);
            acc += __shfl_xor_sync(0xffffffffu, acc, 4);
            const float hn = fast_tanh(acc + bsum);

            if (c == 0) {
                if (so != L_DIM - 1) {            // last step's h is never consumed
#pragma unroll
                    for (int r = 0; r < CLUSTER; r++) st_async_f32(rh0[r], hn, rm0[r]);
                }
                const int ll = dir ? (L_DIM - 1 - so) : so;
                out[((size_t)(n * L_DIM + ll)) * (2 * H_DIM) + dir * H_DIM + j] = hn;
            }
        }
    }
    // No remote traffic in flight (final push skipped); keep smem alive until
    // every CTA is done.
    asm volatile("barrier.cluster.arrive.aligned;" ::: "memory");
    asm volatile("barrier.cluster.wait.aligned;"   ::: "memory");
}

extern "C" void kernel_launch(void* const* d_in, const int* in_sizes, int n_in,
                              void* d_out, int out_size)
{
    (void)in_sizes; (void)n_in; (void)out_size;
    const float* x    = (const float*)d_in[0];
    const float* Wih  = (const float*)d_in[1];
    const float* Whh  = (const float*)d_in[2];
    const float* bih  = (const float*)d_in[3];
    const float* bhh  = (const float*)d_in[4];
    const float* init = (const float*)d_in[5];
    float* out = (float*)d_out;

    rnn_bidir_kernel<<<16 * CLUSTER, THREADS>>>(x, Wih, Whh, bih, bhh, init, out);
}